// round 12
// baseline (speedup 1.0000x reference)
#include <cuda_runtime.h>
#include <cuda_bf16.h>
#include <math.h>

// ---------------- problem constants ----------------
#define NMAX 50000
#define EMAX 800000
#define D 128
#define NH 4
#define HC 32

// ---------------- scratch pool (lifetime-carved) ----------------
// slot size S = NMAX*128
//  [0,S)      h_mod            (later reused as y1 = aggr@Wp)
//  [S,2S)     xl               (live through edge pass C)
//  [2S,3S)    xe               (later reused as z = LayerNorm(y1))
//  [3S,4S)    gA = xl+xe       (dead after pass A; reused as z2 lower half)
//  [4S,5S)    gB = xr-xe       (dead after pass A; reused as z2 upper half)
//  [5S, +4E)  logit / ex
//  then aggr (S), denom (4N), amax enc (4N), misc (style 256, bpp 128, zeros)
#define SLOT ((size_t)NMAX * 128)
#define OFF_HMOD   ((size_t)0)
#define OFF_XL     (SLOT)
#define OFF_XE     (2 * SLOT)
#define OFF_GA     (3 * SLOT)
#define OFF_GB     (4 * SLOT)
#define OFF_LOGIT  (5 * SLOT)
#define OFF_AGGR   (OFF_LOGIT + (size_t)EMAX * 4)
#define OFF_DENOM  (OFF_AGGR + SLOT)
#define OFF_AMAX   (OFF_DENOM + (size_t)NMAX * 4)
#define OFF_MISC   (OFF_AMAX + (size_t)NMAX * 4)
#define POOL_TOTAL (OFF_MISC + 1024)

__device__ __align__(16) float g_pool[POOL_TOTAL];

// ---------------- helpers ----------------
__device__ __forceinline__ unsigned enc_float(float f) {
    unsigned u = __float_as_uint(f);
    return (u & 0x80000000u) ? ~u : (u | 0x80000000u);
}
__device__ __forceinline__ float dec_float(unsigned u) {
    return (u & 0x80000000u) ? __uint_as_float(u ^ 0x80000000u)
                             : __uint_as_float(~u);
}
__device__ __forceinline__ float gelu_exact(float x) {
    return 0.5f * x * (1.0f + erff(x * 0.70710678118654752f));
}

// ---------------- zero accumulators ----------------
__global__ void zero_k(unsigned* __restrict__ amax, float* __restrict__ denom,
                       float* __restrict__ aggr, int n) {
    int i = blockIdx.x * blockDim.x + threadIdx.x;
    int stride = gridDim.x * blockDim.x;
    int n4 = n * 4;
    for (int j = i; j < n4; j += stride) { amax[j] = 0u; denom[j] = 0.0f; }
    int n128 = n * 128;
    for (int j = i; j < n128; j += stride) aggr[j] = 0.0f;
}

// ---------------- tiny precompute: style = t_emb@fc_W+fc_b ; bpp = gat_b@Wp+bp
__global__ void prep_k(const float* __restrict__ t_emb, const float* __restrict__ fc_W,
                       const float* __restrict__ fc_b, const float* __restrict__ gat_b,
                       const float* __restrict__ Wp, const float* __restrict__ bp,
                       float* __restrict__ style, float* __restrict__ bpp) {
    int j = threadIdx.x;  // 384 threads
    if (j < 256) {
        float s = fc_b[j];
        #pragma unroll 4
        for (int k = 0; k < 128; k++) s += t_emb[k] * fc_W[k * 256 + j];
        style[j] = s;
    } else {
        int c = j - 256;
        float s = bp[c];
        #pragma unroll 4
        for (int k = 0; k < 128; k++) s += gat_b[k] * Wp[k * 128 + c];
        bpp[c] = s;
    }
}

// ---------------- AdaGN: GroupNorm(G=8) + style modulation ----------------
__global__ void adagn_k(const float* __restrict__ hs, const float* __restrict__ gn_w,
                        const float* __restrict__ gn_b, const float* __restrict__ style,
                        float* __restrict__ hmod, int n) {
    int node = blockIdx.x;
    int t = threadIdx.x;  // 128 threads = 128 channels
    float x = hs[(size_t)node * 128 + t];
    float s = x, s2 = x * x;
    #pragma unroll
    for (int w = 8; w >= 1; w >>= 1) {  // reduce within 16-lane groups
        s  += __shfl_xor_sync(0xffffffffu, s, w);
        s2 += __shfl_xor_sync(0xffffffffu, s2, w);
    }
    float mu  = s * (1.0f / 16.0f);
    float var = s2 * (1.0f / 16.0f) - mu * mu;
    float nx  = (x - mu) * rsqrtf(var + 1e-5f);
    float g = style[t], b = style[128 + t];
    hmod[(size_t)node * 128 + t] = (nx * gn_w[t] + gn_b[t]) * (1.0f + g) + b;
}

// ---------------- SGEMM: C(MxN) = A(MxK) @ B(KxN) + bias, with epilogue ----
// EPI 0: +bias ;  EPI 1: gelu(+bias) ;  EPI 2: +bias + R (residual)
template <int EPI>
__global__ __launch_bounds__(256)
void sgemm_k(const float* __restrict__ A, int K, const float* __restrict__ B,
             const float* __restrict__ bias, const float* __restrict__ R,
             float* __restrict__ C, int M, int Nout) {
    __shared__ float As[16][128];
    __shared__ float Bs[16][128];
    int t = threadIdx.x;
    int m0 = blockIdx.x * 128;
    int n0 = blockIdx.y * 128;
    int ty = t >> 4, tx = t & 15;
    float acc[8][8];
    #pragma unroll
    for (int i = 0; i < 8; i++)
        #pragma unroll
        for (int j = 0; j < 8; j++) acc[i][j] = 0.0f;

    for (int k0 = 0; k0 < K; k0 += 16) {
        #pragma unroll
        for (int r = 0; r < 2; r++) {
            int idx = t + r * 256;
            int ar = idx >> 2;
            int ac = (idx & 3) * 4;
            float4 v = make_float4(0.f, 0.f, 0.f, 0.f);
            int gr = m0 + ar;
            if (gr < M) v = *(const float4*)(A + (size_t)gr * K + k0 + ac);
            As[ac + 0][ar] = v.x; As[ac + 1][ar] = v.y;
            As[ac + 2][ar] = v.z; As[ac + 3][ar] = v.w;
        }
        #pragma unroll
        for (int r = 0; r < 2; r++) {
            int idx = t + r * 256;
            int brr = idx >> 5;
            int bc = (idx & 31) * 4;
            float4 v = *(const float4*)(B + (size_t)(k0 + brr) * Nout + n0 + bc);
            *(float4*)&Bs[brr][bc] = v;
        }
        __syncthreads();
        #pragma unroll
        for (int kk = 0; kk < 16; kk++) {
            float a[8], b[8];
            *(float4*)&a[0] = *(const float4*)&As[kk][ty * 8];
            *(float4*)&a[4] = *(const float4*)&As[kk][ty * 8 + 4];
            *(float4*)&b[0] = *(const float4*)&Bs[kk][tx * 8];
            *(float4*)&b[4] = *(const float4*)&Bs[kk][tx * 8 + 4];
            #pragma unroll
            for (int i = 0; i < 8; i++)
                #pragma unroll
                for (int j = 0; j < 8; j++) acc[i][j] += a[i] * b[j];
        }
        __syncthreads();
    }

    #pragma unroll
    for (int i = 0; i < 8; i++) {
        int gr = m0 + ty * 8 + i;
        if (gr >= M) break;
        #pragma unroll
        for (int j = 0; j < 8; j += 4) {
            int gc = n0 + tx * 8 + j;
            float o[4];
            #pragma unroll
            for (int q = 0; q < 4; q++) {
                float v = acc[i][j + q] + bias[gc + q];
                if (EPI == 1) v = gelu_exact(v);
                if (EPI == 2) v += R[(size_t)gr * Nout + gc + q];
                o[q] = v;
            }
            *(float4*)(C + (size_t)gr * Nout + gc) =
                make_float4(o[0], o[1], o[2], o[3]);
        }
    }
}

// ---------------- combine: gA = xl + xe ; gB = gB - xe (gB held xr) -------
__global__ void combine_k(const float* __restrict__ xl, const float* __restrict__ xe,
                          float* __restrict__ gA, float* __restrict__ gB, int n128_4) {
    int i = blockIdx.x * blockDim.x + threadIdx.x;
    int stride = gridDim.x * blockDim.x;
    const float4* xl4 = (const float4*)xl;
    const float4* xe4 = (const float4*)xe;
    float4* gA4 = (float4*)gA;
    float4* gB4 = (float4*)gB;
    for (int j = i; j < n128_4; j += stride) {
        float4 l = xl4[j], e = xe4[j], r = gB4[j];
        gA4[j] = make_float4(l.x + e.x, l.y + e.y, l.z + e.z, l.w + e.w);
        gB4[j] = make_float4(r.x - e.x, r.y - e.y, r.z - e.z, r.w - e.w);
    }
}

// ---------------- edge pass A: logits + segment max (warp/edge) -----------
__global__ void edge_logits_k(const int* __restrict__ ei, const float* __restrict__ pos,
                              const float* __restrict__ gA, const float* __restrict__ gB,
                              const float* __restrict__ We, const float* __restrict__ att,
                              float* __restrict__ logit, unsigned* __restrict__ amax, int E) {
    __shared__ float sW0[128], sW1[128], sAtt[128];
    int t = threadIdx.x;
    if (t < 128) {
        sW0[t]  = We[128 * 128 + t];
        sW1[t]  = We[129 * 128 + t];
        sAtt[t] = att[t];
    }
    __syncthreads();
    int e = (blockIdx.x * blockDim.x + t) >> 5;
    if (e >= E) return;
    int l = t & 31;
    int s = ei[e], d = ei[E + e];
    float2 ps = *(const float2*)(pos + 2 * (size_t)s);
    float2 pd = *(const float2*)(pos + 2 * (size_t)d);
    float rx = ps.x - pd.x, ry = ps.y - pd.y;
    float inv = 1.0f / (rx * rx + ry * ry + 1e-8f);
    float ox = -ry * inv, oy = rx * inv;
    const float* as = gA + (size_t)s * 128;
    const float* bd = gB + (size_t)d * 128;
    float p[4];
    #pragma unroll
    for (int k = 0; k < 4; k++) {
        int ch = k * 32 + l;
        float v = as[ch] + bd[ch] + ox * sW0[ch] + oy * sW1[ch];
        v = v > 0.0f ? v : 0.2f * v;          // leaky_relu(0.2)
        p[k] = v * sAtt[ch];
    }
    #pragma unroll
    for (int w = 16; w >= 1; w >>= 1) {
        #pragma unroll
        for (int k = 0; k < 4; k++) p[k] += __shfl_xor_sync(0xffffffffu, p[k], w);
    }
    if (l == 0)
        *(float4*)(logit + (size_t)e * 4) = make_float4(p[0], p[1], p[2], p[3]);
    if (l < 4)
        atomicMax(&amax[(size_t)d * 4 + l], enc_float(p[l]));
}

// ---------------- edge pass B: ex = exp(logit - max), denom += ex ---------
__global__ void edge_exp_k(const int* __restrict__ ei, float* __restrict__ lg,
                           const unsigned* __restrict__ amax, float* __restrict__ denom, int E) {
    int e = blockIdx.x * blockDim.x + threadIdx.x;
    if (e >= E) return;
    int d = ei[E + e];
    float4 v = *(float4*)(lg + (size_t)e * 4);
    float r[4] = {v.x, v.y, v.z, v.w};
    #pragma unroll
    for (int k = 0; k < 4; k++) {
        float am = dec_float(amax[(size_t)d * 4 + k]);
        float ex = expf(r[k] - am);
        r[k] = ex;
        atomicAdd(&denom[(size_t)d * 4 + k], ex);
    }
    *(float4*)(lg + (size_t)e * 4) = make_float4(r[0], r[1], r[2], r[3]);
}

// ---------------- edge pass C: aggr[dst] += alpha * xl[src] (warp/edge) ---
__global__ void edge_aggr_k(const int* __restrict__ ei, const float* __restrict__ lg,
                            const float* __restrict__ denom, const float* __restrict__ xl,
                            float* __restrict__ aggr, int E) {
    int t = threadIdx.x;
    int e = (blockIdx.x * blockDim.x + t) >> 5;
    if (e >= E) return;
    int l = t & 31;
    int s = ei[e], d = ei[E + e];
    float4 ex = *(const float4*)(lg + (size_t)e * 4);
    float al[4];
    al[0] = ex.x / (denom[(size_t)d * 4 + 0] + 1e-16f);
    al[1] = ex.y / (denom[(size_t)d * 4 + 1] + 1e-16f);
    al[2] = ex.z / (denom[(size_t)d * 4 + 2] + 1e-16f);
    al[3] = ex.w / (denom[(size_t)d * 4 + 3] + 1e-16f);
    const float* xs = xl + (size_t)s * 128;
    float* od = aggr + (size_t)d * 128;
    #pragma unroll
    for (int k = 0; k < 4; k++) {
        int ch = k * 32 + l;
        atomicAdd(&od[ch], al[k] * xs[ch]);
    }
}

// ---------------- LayerNorm over D=128 ----------------
__global__ void ln_k(const float* __restrict__ y, const float* __restrict__ w,
                     const float* __restrict__ b, float* __restrict__ z, int n) {
    int node = blockIdx.x;
    int t = threadIdx.x;  // 128
    float x = y[(size_t)node * 128 + t];
    float s = x, s2 = x * x;
    #pragma unroll
    for (int wdt = 16; wdt >= 1; wdt >>= 1) {
        s  += __shfl_xor_sync(0xffffffffu, s, wdt);
        s2 += __shfl_xor_sync(0xffffffffu, s2, wdt);
    }
    __shared__ float ss[4], ss2[4];
    int wid = t >> 5;
    if ((t & 31) == 0) { ss[wid] = s; ss2[wid] = s2; }
    __syncthreads();
    s  = ss[0] + ss[1] + ss[2] + ss[3];
    s2 = ss2[0] + ss2[1] + ss2[2] + ss2[3];
    float mu  = s * (1.0f / 128.0f);
    float var = s2 * (1.0f / 128.0f) - mu * mu;
    z[(size_t)node * 128 + t] = (x - mu) * rsqrtf(var + 1e-5f) * w[t] + b[t];
}

// ---------------- launch ----------------
extern "C" void kernel_launch(void* const* d_in, const int* in_sizes, int n_in,
                              void* d_out, int out_size) {
    const float* h_target = (const float*)d_in[0];
    const float* h_source = (const float*)d_in[1];
    const int*   ei       = (const int*)d_in[2];   // int32! (JAX x64 disabled)
    const float* pos      = (const float*)d_in[3];
    const float* t_emb    = (const float*)d_in[4];
    const float* gn_w     = (const float*)d_in[5];
    const float* gn_b     = (const float*)d_in[6];
    const float* fc_W     = (const float*)d_in[7];
    const float* fc_b     = (const float*)d_in[8];
    const float* Wl       = (const float*)d_in[9];
    const float* bl       = (const float*)d_in[10];
    const float* Wr       = (const float*)d_in[11];
    const float* br       = (const float*)d_in[12];
    const float* We       = (const float*)d_in[13];
    const float* att      = (const float*)d_in[14];
    const float* gat_b    = (const float*)d_in[15];
    const float* Wp       = (const float*)d_in[16];
    const float* bp       = (const float*)d_in[17];
    const float* ln_w     = (const float*)d_in[18];
    const float* ln_b     = (const float*)d_in[19];
    const float* W1       = (const float*)d_in[20];
    const float* b1       = (const float*)d_in[21];
    const float* W2       = (const float*)d_in[22];
    const float* b2       = (const float*)d_in[23];

    int n = in_sizes[0] / 128;
    int e = in_sizes[2] / 2;

    float* pool = nullptr;
    cudaGetSymbolAddress((void**)&pool, g_pool);
    float*    g_hmod  = pool + OFF_HMOD;   // later y1
    float*    g_xl    = pool + OFF_XL;
    float*    g_xe    = pool + OFF_XE;     // later z
    float*    g_gA    = pool + OFF_GA;     // later z2 (spans gA+gB)
    float*    g_gB    = pool + OFF_GB;
    float*    g_logit = pool + OFF_LOGIT;
    float*    g_aggr  = pool + OFF_AGGR;
    float*    g_denom = pool + OFF_DENOM;
    unsigned* g_amax  = (unsigned*)(pool + OFF_AMAX);
    float*    g_style = pool + OFF_MISC;
    float*    g_bpp   = pool + OFF_MISC + 256;
    float*    g_zeros = pool + OFF_MISC + 384;  // never written: stays 0
    float*    g_y1    = g_hmod;
    float*    g_z     = g_xe;
    float*    g_z2    = g_gA;

    int mblocks = (n + 127) / 128;

    // 0) reset accumulators for this replay
    zero_k<<<512, 256>>>(g_amax, g_denom, g_aggr, n);
    // 1) tiny precompute
    prep_k<<<1, 384>>>(t_emb, fc_W, fc_b, gat_b, Wp, bp, g_style, g_bpp);
    // 2) AdaGN
    adagn_k<<<n, 128>>>(h_source, gn_w, gn_b, g_style, g_hmod, n);
    // 3) node GEMMs: xl = hmod@Wl+bl ; xr(into gB) = hmod@Wr+br ; xe = hmod@We_phys
    sgemm_k<0><<<dim3(mblocks, 1), 256>>>(g_hmod, 128, Wl, bl, nullptr, g_xl, n, 128);
    sgemm_k<0><<<dim3(mblocks, 1), 256>>>(g_hmod, 128, Wr, br, nullptr, g_gB, n, 128);
    sgemm_k<0><<<dim3(mblocks, 1), 256>>>(g_hmod, 128, We, g_zeros, nullptr, g_xe, n, 128);
    // 4) combine: gA = xl+xe ; gB = xr-xe
    combine_k<<<512, 256>>>(g_xl, g_xe, g_gA, g_gB, n * 32);
    // 5) edge passes
    int eblocks = (e + 7) / 8;
    edge_logits_k<<<eblocks, 256>>>(ei, pos, g_gA, g_gB, We, att, g_logit, g_amax, e);
    edge_exp_k<<<(e + 255) / 256, 256>>>(ei, g_logit, g_amax, g_denom, e);
    edge_aggr_k<<<eblocks, 256>>>(ei, g_logit, g_denom, g_xl, g_aggr, e);
    // 6) post-GAT: y1 = aggr@Wp + (gat_b@Wp + bp)
    sgemm_k<0><<<dim3(mblocks, 1), 256>>>(g_aggr, 128, Wp, g_bpp, nullptr, g_y1, n, 128);
    // 7) LayerNorm
    ln_k<<<n, 128>>>(g_y1, ln_w, ln_b, g_z, n);
    // 8) z2 = gelu(z@W1 + b1)
    sgemm_k<1><<<dim3(mblocks, 2), 256>>>(g_z, 128, W1, b1, nullptr, g_z2, n, 256);
    // 9) out = z2@W2 + b2 + h_target
    sgemm_k<2><<<dim3(mblocks, 1), 256>>>(g_z2, 256, W2, b2, h_target, (float*)d_out, n, 128);
}

// round 15
// speedup vs baseline: 1.0000x; 1.0000x over previous
#include <cuda_runtime.h>
#include <cuda_bf16.h>
#include <math.h>

// ---------------- problem constants ----------------
#define NMAX 50000
#define EMAX 800000
#define D 128
#define NH 4
#define HC 32

// ---------------- scratch pool (lifetime-carved) ----------------
// slot size S = NMAX*128
//  [0,S)      h_mod            (later reused as y1 = aggr@Wp)
//  [S,2S)     xl               (live through edge pass C)
//  [2S,3S)    xe               (later reused as z = LayerNorm(y1))
//  [3S,4S)    gA = xl+xe       (dead after pass A; reused as z2 lower half)
//  [4S,5S)    gB = xr-xe       (dead after pass A; reused as z2 upper half)
//  [5S, +4E)  logit / ex
//  then aggr (S), denom (4N), amax enc (4N), misc (style 256, bpp 128, zeros)
#define SLOT ((size_t)NMAX * 128)
#define OFF_HMOD   ((size_t)0)
#define OFF_XL     (SLOT)
#define OFF_XE     (2 * SLOT)
#define OFF_GA     (3 * SLOT)
#define OFF_GB     (4 * SLOT)
#define OFF_LOGIT  (5 * SLOT)
#define OFF_AGGR   (OFF_LOGIT + (size_t)EMAX * 4)
#define OFF_DENOM  (OFF_AGGR + SLOT)
#define OFF_AMAX   (OFF_DENOM + (size_t)NMAX * 4)
#define OFF_MISC   (OFF_AMAX + (size_t)NMAX * 4)
#define POOL_TOTAL (OFF_MISC + 1024)

__device__ __align__(16) float g_pool[POOL_TOTAL];

// ---------------- helpers ----------------
__device__ __forceinline__ unsigned enc_float(float f) {
    unsigned u = __float_as_uint(f);
    return (u & 0x80000000u) ? ~u : (u | 0x80000000u);
}
__device__ __forceinline__ float dec_float(unsigned u) {
    return (u & 0x80000000u) ? __uint_as_float(u ^ 0x80000000u)
                             : __uint_as_float(~u);
}
__device__ __forceinline__ float gelu_exact(float x) {
    return 0.5f * x * (1.0f + erff(x * 0.70710678118654752f));
}

// ---------------- zero accumulators ----------------
__global__ void zero_k(unsigned* __restrict__ amax, float* __restrict__ denom,
                       float* __restrict__ aggr, int n) {
    int i = blockIdx.x * blockDim.x + threadIdx.x;
    int stride = gridDim.x * blockDim.x;
    int n4 = n * 4;
    for (int j = i; j < n4; j += stride) { amax[j] = 0u; denom[j] = 0.0f; }
    int n128 = n * 128;
    for (int j = i; j < n128; j += stride) aggr[j] = 0.0f;
}

// ---------------- tiny precompute: style = t_emb@fc_W+fc_b ; bpp = gat_b@Wp+bp
__global__ void prep_k(const float* __restrict__ t_emb, const float* __restrict__ fc_W,
                       const float* __restrict__ fc_b, const float* __restrict__ gat_b,
                       const float* __restrict__ Wp, const float* __restrict__ bp,
                       float* __restrict__ style, float* __restrict__ bpp) {
    int j = threadIdx.x;  // 384 threads
    if (j < 256) {
        float s = fc_b[j];
        #pragma unroll 4
        for (int k = 0; k < 128; k++) s += t_emb[k] * fc_W[k * 256 + j];
        style[j] = s;
    } else {
        int c = j - 256;
        float s = bp[c];
        #pragma unroll 4
        for (int k = 0; k < 128; k++) s += gat_b[k] * Wp[k * 128 + c];
        bpp[c] = s;
    }
}

// ---------------- AdaGN: GroupNorm(G=8) + style modulation ----------------
__global__ void adagn_k(const float* __restrict__ hs, const float* __restrict__ gn_w,
                        const float* __restrict__ gn_b, const float* __restrict__ style,
                        float* __restrict__ hmod, int n) {
    int node = blockIdx.x;
    int t = threadIdx.x;  // 128 threads = 128 channels
    float x = hs[(size_t)node * 128 + t];
    float s = x, s2 = x * x;
    #pragma unroll
    for (int w = 8; w >= 1; w >>= 1) {  // reduce within 16-lane groups
        s  += __shfl_xor_sync(0xffffffffu, s, w);
        s2 += __shfl_xor_sync(0xffffffffu, s2, w);
    }
    float mu  = s * (1.0f / 16.0f);
    float var = s2 * (1.0f / 16.0f) - mu * mu;
    float nx  = (x - mu) * rsqrtf(var + 1e-5f);
    float g = style[t], b = style[128 + t];
    hmod[(size_t)node * 128 + t] = (nx * gn_w[t] + gn_b[t]) * (1.0f + g) + b;
}

// ---------------- SGEMM: C(MxN) = A(MxK) @ B(KxN) + bias, with epilogue ----
// EPI 0: +bias ;  EPI 1: gelu(+bias) ;  EPI 2: +bias + R (residual)
template <int EPI>
__global__ __launch_bounds__(256)
void sgemm_k(const float* __restrict__ A, int K, const float* __restrict__ B,
             const float* __restrict__ bias, const float* __restrict__ R,
             float* __restrict__ C, int M, int Nout) {
    __shared__ float As[16][128];
    __shared__ float Bs[16][128];
    int t = threadIdx.x;
    int m0 = blockIdx.x * 128;
    int n0 = blockIdx.y * 128;
    int ty = t >> 4, tx = t & 15;
    float acc[8][8];
    #pragma unroll
    for (int i = 0; i < 8; i++)
        #pragma unroll
        for (int j = 0; j < 8; j++) acc[i][j] = 0.0f;

    for (int k0 = 0; k0 < K; k0 += 16) {
        #pragma unroll
        for (int r = 0; r < 2; r++) {
            int idx = t + r * 256;
            int ar = idx >> 2;
            int ac = (idx & 3) * 4;
            float4 v = make_float4(0.f, 0.f, 0.f, 0.f);
            int gr = m0 + ar;
            if (gr < M) v = *(const float4*)(A + (size_t)gr * K + k0 + ac);
            As[ac + 0][ar] = v.x; As[ac + 1][ar] = v.y;
            As[ac + 2][ar] = v.z; As[ac + 3][ar] = v.w;
        }
        #pragma unroll
        for (int r = 0; r < 2; r++) {
            int idx = t + r * 256;
            int brr = idx >> 5;
            int bc = (idx & 31) * 4;
            float4 v = *(const float4*)(B + (size_t)(k0 + brr) * Nout + n0 + bc);
            *(float4*)&Bs[brr][bc] = v;
        }
        __syncthreads();
        #pragma unroll
        for (int kk = 0; kk < 16; kk++) {
            float a[8], b[8];
            *(float4*)&a[0] = *(const float4*)&As[kk][ty * 8];
            *(float4*)&a[4] = *(const float4*)&As[kk][ty * 8 + 4];
            *(float4*)&b[0] = *(const float4*)&Bs[kk][tx * 8];
            *(float4*)&b[4] = *(const float4*)&Bs[kk][tx * 8 + 4];
            #pragma unroll
            for (int i = 0; i < 8; i++)
                #pragma unroll
                for (int j = 0; j < 8; j++) acc[i][j] += a[i] * b[j];
        }
        __syncthreads();
    }

    #pragma unroll
    for (int i = 0; i < 8; i++) {
        int gr = m0 + ty * 8 + i;
        if (gr >= M) break;
        #pragma unroll
        for (int j = 0; j < 8; j += 4) {
            int gc = n0 + tx * 8 + j;
            float o[4];
            #pragma unroll
            for (int q = 0; q < 4; q++) {
                float v = acc[i][j + q] + bias[gc + q];
                if (EPI == 1) v = gelu_exact(v);
                if (EPI == 2) v += R[(size_t)gr * Nout + gc + q];
                o[q] = v;
            }
            *(float4*)(C + (size_t)gr * Nout + gc) =
                make_float4(o[0], o[1], o[2], o[3]);
        }
    }
}

// ---------------- combine: gA = xl + xe ; gB = gB - xe (gB held xr) -------
__global__ void combine_k(const float* __restrict__ xl, const float* __restrict__ xe,
                          float* __restrict__ gA, float* __restrict__ gB, int n128_4) {
    int i = blockIdx.x * blockDim.x + threadIdx.x;
    int stride = gridDim.x * blockDim.x;
    const float4* xl4 = (const float4*)xl;
    const float4* xe4 = (const float4*)xe;
    float4* gA4 = (float4*)gA;
    float4* gB4 = (float4*)gB;
    for (int j = i; j < n128_4; j += stride) {
        float4 l = xl4[j], e = xe4[j], r = gB4[j];
        gA4[j] = make_float4(l.x + e.x, l.y + e.y, l.z + e.z, l.w + e.w);
        gB4[j] = make_float4(r.x - e.x, r.y - e.y, r.z - e.z, r.w - e.w);
    }
}

// ---------------- edge pass A: logits + segment max (warp/edge) -----------
__global__ void edge_logits_k(const int* __restrict__ ei, const float* __restrict__ pos,
                              const float* __restrict__ gA, const float* __restrict__ gB,
                              const float* __restrict__ We, const float* __restrict__ att,
                              float* __restrict__ logit, unsigned* __restrict__ amax, int E) {
    __shared__ float sW0[128], sW1[128], sAtt[128];
    int t = threadIdx.x;
    if (t < 128) {
        sW0[t]  = We[128 * 128 + t];
        sW1[t]  = We[129 * 128 + t];
        sAtt[t] = att[t];
    }
    __syncthreads();
    int e = (blockIdx.x * blockDim.x + t) >> 5;
    if (e >= E) return;
    int l = t & 31;
    int s = ei[e], d = ei[E + e];
    float2 ps = *(const float2*)(pos + 2 * (size_t)s);
    float2 pd = *(const float2*)(pos + 2 * (size_t)d);
    float rx = ps.x - pd.x, ry = ps.y - pd.y;
    float inv = 1.0f / (rx * rx + ry * ry + 1e-8f);
    float ox = -ry * inv, oy = rx * inv;
    const float* as = gA + (size_t)s * 128;
    const float* bd = gB + (size_t)d * 128;
    float p[4];
    #pragma unroll
    for (int k = 0; k < 4; k++) {
        int ch = k * 32 + l;
        float v = as[ch] + bd[ch] + ox * sW0[ch] + oy * sW1[ch];
        v = v > 0.0f ? v : 0.2f * v;          // leaky_relu(0.2)
        p[k] = v * sAtt[ch];
    }
    #pragma unroll
    for (int w = 16; w >= 1; w >>= 1) {
        #pragma unroll
        for (int k = 0; k < 4; k++) p[k] += __shfl_xor_sync(0xffffffffu, p[k], w);
    }
    if (l == 0)
        *(float4*)(logit + (size_t)e * 4) = make_float4(p[0], p[1], p[2], p[3]);
    if (l < 4)
        atomicMax(&amax[(size_t)d * 4 + l], enc_float(p[l]));
}

// ---------------- edge pass B: ex = exp(logit - max), denom += ex ---------
__global__ void edge_exp_k(const int* __restrict__ ei, float* __restrict__ lg,
                           const unsigned* __restrict__ amax, float* __restrict__ denom, int E) {
    int e = blockIdx.x * blockDim.x + threadIdx.x;
    if (e >= E) return;
    int d = ei[E + e];
    float4 v = *(float4*)(lg + (size_t)e * 4);
    float r[4] = {v.x, v.y, v.z, v.w};
    #pragma unroll
    for (int k = 0; k < 4; k++) {
        float am = dec_float(amax[(size_t)d * 4 + k]);
        float ex = expf(r[k] - am);
        r[k] = ex;
        atomicAdd(&denom[(size_t)d * 4 + k], ex);
    }
    *(float4*)(lg + (size_t)e * 4) = make_float4(r[0], r[1], r[2], r[3]);
}

// ---------------- edge pass C: aggr[dst] += alpha * xl[src] (warp/edge) ---
__global__ void edge_aggr_k(const int* __restrict__ ei, const float* __restrict__ lg,
                            const float* __restrict__ denom, const float* __restrict__ xl,
                            float* __restrict__ aggr, int E) {
    int t = threadIdx.x;
    int e = (blockIdx.x * blockDim.x + t) >> 5;
    if (e >= E) return;
    int l = t & 31;
    int s = ei[e], d = ei[E + e];
    float4 ex = *(const float4*)(lg + (size_t)e * 4);
    float al[4];
    al[0] = ex.x / (denom[(size_t)d * 4 + 0] + 1e-16f);
    al[1] = ex.y / (denom[(size_t)d * 4 + 1] + 1e-16f);
    al[2] = ex.z / (denom[(size_t)d * 4 + 2] + 1e-16f);
    al[3] = ex.w / (denom[(size_t)d * 4 + 3] + 1e-16f);
    const float* xs = xl + (size_t)s * 128;
    float* od = aggr + (size_t)d * 128;
    #pragma unroll
    for (int k = 0; k < 4; k++) {
        int ch = k * 32 + l;
        atomicAdd(&od[ch], al[k] * xs[ch]);
    }
}

// ---------------- LayerNorm over D=128 ----------------
__global__ void ln_k(const float* __restrict__ y, const float* __restrict__ w,
                     const float* __restrict__ b, float* __restrict__ z, int n) {
    int node = blockIdx.x;
    int t = threadIdx.x;  // 128
    float x = y[(size_t)node * 128 + t];
    float s = x, s2 = x * x;
    #pragma unroll
    for (int wdt = 16; wdt >= 1; wdt >>= 1) {
        s  += __shfl_xor_sync(0xffffffffu, s, wdt);
        s2 += __shfl_xor_sync(0xffffffffu, s2, wdt);
    }
    __shared__ float ss[4], ss2[4];
    int wid = t >> 5;
    if ((t & 31) == 0) { ss[wid] = s; ss2[wid] = s2; }
    __syncthreads();
    s  = ss[0] + ss[1] + ss[2] + ss[3];
    s2 = ss2[0] + ss2[1] + ss2[2] + ss2[3];
    float mu  = s * (1.0f / 128.0f);
    float var = s2 * (1.0f / 128.0f) - mu * mu;
    z[(size_t)node * 128 + t] = (x - mu) * rsqrtf(var + 1e-5f) * w[t] + b[t];
}

// ---------------- launch ----------------
extern "C" void kernel_launch(void* const* d_in, const int* in_sizes, int n_in,
                              void* d_out, int out_size) {
    const float* h_target = (const float*)d_in[0];
    const float* h_source = (const float*)d_in[1];
    const int*   ei       = (const int*)d_in[2];   // int32! (JAX x64 disabled)
    const float* pos      = (const float*)d_in[3];
    const float* t_emb    = (const float*)d_in[4];
    const float* gn_w     = (const float*)d_in[5];
    const float* gn_b     = (const float*)d_in[6];
    const float* fc_W     = (const float*)d_in[7];
    const float* fc_b     = (const float*)d_in[8];
    const float* Wl       = (const float*)d_in[9];
    const float* bl       = (const float*)d_in[10];
    const float* Wr       = (const float*)d_in[11];
    const float* br       = (const float*)d_in[12];
    const float* We       = (const float*)d_in[13];
    const float* att      = (const float*)d_in[14];
    const float* gat_b    = (const float*)d_in[15];
    const float* Wp       = (const float*)d_in[16];
    const float* bp       = (const float*)d_in[17];
    const float* ln_w     = (const float*)d_in[18];
    const float* ln_b     = (const float*)d_in[19];
    const float* W1       = (const float*)d_in[20];
    const float* b1       = (const float*)d_in[21];
    const float* W2       = (const float*)d_in[22];
    const float* b2       = (const float*)d_in[23];

    int n = in_sizes[0] / 128;
    int e = in_sizes[2] / 2;

    float* pool = nullptr;
    cudaGetSymbolAddress((void**)&pool, g_pool);
    float*    g_hmod  = pool + OFF_HMOD;   // later y1
    float*    g_xl    = pool + OFF_XL;
    float*    g_xe    = pool + OFF_XE;     // later z
    float*    g_gA    = pool + OFF_GA;     // later z2 (spans gA+gB)
    float*    g_gB    = pool + OFF_GB;
    float*    g_logit = pool + OFF_LOGIT;
    float*    g_aggr  = pool + OFF_AGGR;
    float*    g_denom = pool + OFF_DENOM;
    unsigned* g_amax  = (unsigned*)(pool + OFF_AMAX);
    float*    g_style = pool + OFF_MISC;
    float*    g_bpp   = pool + OFF_MISC + 256;
    float*    g_zeros = pool + OFF_MISC + 384;  // never written: stays 0
    float*    g_y1    = g_hmod;
    float*    g_z     = g_xe;
    float*    g_z2    = g_gA;

    int mblocks = (n + 127) / 128;

    // 0) reset accumulators for this replay
    zero_k<<<512, 256>>>(g_amax, g_denom, g_aggr, n);
    // 1) tiny precompute
    prep_k<<<1, 384>>>(t_emb, fc_W, fc_b, gat_b, Wp, bp, g_style, g_bpp);
    // 2) AdaGN
    adagn_k<<<n, 128>>>(h_source, gn_w, gn_b, g_style, g_hmod, n);
    // 3) node GEMMs: xl = hmod@Wl+bl ; xr(into gB) = hmod@Wr+br ; xe = hmod@We_phys
    sgemm_k<0><<<dim3(mblocks, 1), 256>>>(g_hmod, 128, Wl, bl, nullptr, g_xl, n, 128);
    sgemm_k<0><<<dim3(mblocks, 1), 256>>>(g_hmod, 128, Wr, br, nullptr, g_gB, n, 128);
    sgemm_k<0><<<dim3(mblocks, 1), 256>>>(g_hmod, 128, We, g_zeros, nullptr, g_xe, n, 128);
    // 4) combine: gA = xl+xe ; gB = xr-xe
    combine_k<<<512, 256>>>(g_xl, g_xe, g_gA, g_gB, n * 32);
    // 5) edge passes
    int eblocks = (e + 7) / 8;
    edge_logits_k<<<eblocks, 256>>>(ei, pos, g_gA, g_gB, We, att, g_logit, g_amax, e);
    edge_exp_k<<<(e + 255) / 256, 256>>>(ei, g_logit, g_amax, g_denom, e);
    edge_aggr_k<<<eblocks, 256>>>(ei, g_logit, g_denom, g_xl, g_aggr, e);
    // 6) post-GAT: y1 = aggr@Wp + (gat_b@Wp + bp)
    sgemm_k<0><<<dim3(mblocks, 1), 256>>>(g_aggr, 128, Wp, g_bpp, nullptr, g_y1, n, 128);
    // 7) LayerNorm
    ln_k<<<n, 128>>>(g_y1, ln_w, ln_b, g_z, n);
    // 8) z2 = gelu(z@W1 + b1)
    sgemm_k<1><<<dim3(mblocks, 2), 256>>>(g_z, 128, W1, b1, nullptr, g_z2, n, 256);
    // 9) out = z2@W2 + b2 + h_target
    sgemm_k<2><<<dim3(mblocks, 1), 256>>>(g_z2, 256, W2, b2, h_target, (float*)d_out, n, 128);
}

// round 16
// speedup vs baseline: 1.1603x; 1.1602x over previous
#include <cuda_runtime.h>
#include <cuda_bf16.h>
#include <math.h>

// ---------------- problem constants ----------------
#define NMAX 50000
#define EMAX 800000

// ---------------- scratch pool (lifetime-carved) ----------------
// slot S = NMAX*128
//  [0,S)        hmod              (later reused as z = LN(aggr@Wp))
//  [S,4S)       X = [xl|gA|gB] interleaved per row, stride 384
//               (dead after pass C; first 2S reused as z2)
//  [4S,+4E)     logit / ex
//  then aggr (S), denom (4N), amax enc (4N),
//  misc: style 256, bpp 128, bias_cat 384, Bcat 128*384
#define SLOT ((size_t)NMAX * 128)
#define OFF_HMOD   ((size_t)0)
#define OFF_X      (SLOT)
#define OFF_LOGIT  (4 * SLOT)
#define OFF_AGGR   (OFF_LOGIT + (size_t)EMAX * 4)
#define OFF_DENOM  (OFF_AGGR + SLOT)
#define OFF_AMAX   (OFF_DENOM + (size_t)NMAX * 4)
#define OFF_MISC   (OFF_AMAX + (size_t)NMAX * 4)
#define MISC_STYLE 0
#define MISC_BPP   256
#define MISC_BCB   384                      // bias_cat (384)
#define MISC_BCAT  1024                     // Bcat (128*384), 16B aligned
#define POOL_TOTAL (OFF_MISC + 1024 + (size_t)128 * 384 + 256)

__device__ __align__(16) float g_pool[POOL_TOTAL];

// ---------------- helpers ----------------
__device__ __forceinline__ unsigned enc_float(float f) {
    unsigned u = __float_as_uint(f);
    return (u & 0x80000000u) ? ~u : (u | 0x80000000u);
}
__device__ __forceinline__ float dec_float(unsigned u) {
    return (u & 0x80000000u) ? __uint_as_float(u ^ 0x80000000u)
                             : __uint_as_float(~u);
}
__device__ __forceinline__ float gelu_exact(float x) {
    return 0.5f * x * (1.0f + erff(x * 0.70710678118654752f));
}

// ---------------- zero accumulators ----------------
__global__ void zero_k(unsigned* __restrict__ amax, float* __restrict__ denom,
                       float* __restrict__ aggr, int n) {
    int i = blockIdx.x * blockDim.x + threadIdx.x;
    int stride = gridDim.x * blockDim.x;
    int n4 = n * 4;
    for (int j = i; j < n4; j += stride) { amax[j] = 0u; denom[j] = 0.0f; }
    int n128 = n * 128;
    for (int j = i; j < n128; j += stride) aggr[j] = 0.0f;
}

// ---------------- tiny precompute: style = t_emb@fc_W+fc_b ; bpp = gat_b@Wp+bp
__global__ void prep_k(const float* __restrict__ t_emb, const float* __restrict__ fc_W,
                       const float* __restrict__ fc_b, const float* __restrict__ gat_b,
                       const float* __restrict__ Wp, const float* __restrict__ bp,
                       float* __restrict__ style, float* __restrict__ bpp) {
    int j = threadIdx.x;  // 384 threads
    if (j < 256) {
        float s = fc_b[j];
        #pragma unroll 4
        for (int k = 0; k < 128; k++) s += t_emb[k] * fc_W[k * 256 + j];
        style[j] = s;
    } else {
        int c = j - 256;
        float s = bp[c];
        #pragma unroll 4
        for (int k = 0; k < 128; k++) s += gat_b[k] * Wp[k * 128 + c];
        bpp[c] = s;
    }
}

// -------- build Bcat = [Wl | Wl+We_phys | Wr-We_phys] (128x384) + bias_cat --
__global__ void bcat_k(const float* __restrict__ Wl, const float* __restrict__ Wr,
                       const float* __restrict__ We, const float* __restrict__ bl,
                       const float* __restrict__ br, float* __restrict__ Bcat,
                       float* __restrict__ bias_cat) {
    int i = blockIdx.x * blockDim.x + threadIdx.x;
    if (i < 128 * 384) {
        int k = i / 384, c = i % 384;
        float v;
        if (c < 128)      v = Wl[k * 128 + c];
        else if (c < 256) v = Wl[k * 128 + (c - 128)] + We[k * 128 + (c - 128)];
        else              v = Wr[k * 128 + (c - 256)] - We[k * 128 + (c - 256)];
        Bcat[i] = v;
    }
    if (i < 384)
        bias_cat[i] = (i < 128) ? bl[i] : (i < 256 ? bl[i - 128] : br[i - 256]);
}

// ---------------- AdaGN: GroupNorm(G=8) + style modulation ----------------
__global__ void adagn_k(const float* __restrict__ hs, const float* __restrict__ gn_w,
                        const float* __restrict__ gn_b, const float* __restrict__ style,
                        float* __restrict__ hmod, int n) {
    int node = blockIdx.x;
    int t = threadIdx.x;  // 128 threads = 128 channels
    float x = hs[(size_t)node * 128 + t];
    float s = x, s2 = x * x;
    #pragma unroll
    for (int w = 8; w >= 1; w >>= 1) {  // reduce within 16-lane groups
        s  += __shfl_xor_sync(0xffffffffu, s, w);
        s2 += __shfl_xor_sync(0xffffffffu, s2, w);
    }
    float mu  = s * (1.0f / 16.0f);
    float var = s2 * (1.0f / 16.0f) - mu * mu;
    float nx  = (x - mu) * rsqrtf(var + 1e-5f);
    float g = style[t], b = style[128 + t];
    hmod[(size_t)node * 128 + t] = (nx * gn_w[t] + gn_b[t]) * (1.0f + g) + b;
}

// ---------------- SGEMM: C(MxN) = A(MxK) @ B(KxN) + bias, with epilogue ----
// EPI 0: +bias ; 1: gelu(+bias) ; 2: +bias+R (residual) ; 3: LayerNorm(+bias)
template <int EPI>
__global__ __launch_bounds__(256)
void sgemm_k(const float* __restrict__ A, int K, const float* __restrict__ B,
             const float* __restrict__ bias, const float* __restrict__ R,
             const float* __restrict__ P1, const float* __restrict__ P2,
             float* __restrict__ C, int M, int Nout) {
    __shared__ float As[16][128];
    __shared__ float Bs[16][128];
    int t = threadIdx.x;
    int m0 = blockIdx.x * 128;
    int n0 = blockIdx.y * 128;
    int ty = t >> 4, tx = t & 15;
    float acc[8][8];
    #pragma unroll
    for (int i = 0; i < 8; i++)
        #pragma unroll
        for (int j = 0; j < 8; j++) acc[i][j] = 0.0f;

    for (int k0 = 0; k0 < K; k0 += 16) {
        #pragma unroll
        for (int r = 0; r < 2; r++) {
            int idx = t + r * 256;
            int ar = idx >> 2;
            int ac = (idx & 3) * 4;
            float4 v = make_float4(0.f, 0.f, 0.f, 0.f);
            int gr = m0 + ar;
            if (gr < M) v = *(const float4*)(A + (size_t)gr * K + k0 + ac);
            As[ac + 0][ar] = v.x; As[ac + 1][ar] = v.y;
            As[ac + 2][ar] = v.z; As[ac + 3][ar] = v.w;
        }
        #pragma unroll
        for (int r = 0; r < 2; r++) {
            int idx = t + r * 256;
            int brr = idx >> 5;
            int bc = (idx & 31) * 4;
            float4 v = *(const float4*)(B + (size_t)(k0 + brr) * Nout + n0 + bc);
            *(float4*)&Bs[brr][bc] = v;
        }
        __syncthreads();
        #pragma unroll
        for (int kk = 0; kk < 16; kk++) {
            float a[8], b[8];
            *(float4*)&a[0] = *(const float4*)&As[kk][ty * 8];
            *(float4*)&a[4] = *(const float4*)&As[kk][ty * 8 + 4];
            *(float4*)&b[0] = *(const float4*)&Bs[kk][tx * 8];
            *(float4*)&b[4] = *(const float4*)&Bs[kk][tx * 8 + 4];
            #pragma unroll
            for (int i = 0; i < 8; i++)
                #pragma unroll
                for (int j = 0; j < 8; j++) acc[i][j] += a[i] * b[j];
        }
        __syncthreads();
    }

    if (EPI == 3) {
        // Fused LayerNorm over the 128 columns of each row (Nout==128, n0==0).
        // Row gr = m0+ty*8+i is spread over the 16 tx lanes of this ty group;
        // those 16 lanes are contiguous within a warp (lane bits 0..3).
        #pragma unroll
        for (int i = 0; i < 8; i++) {
            float v[8];
            float s = 0.0f, s2 = 0.0f;
            #pragma unroll
            for (int j = 0; j < 8; j++) {
                v[j] = acc[i][j] + bias[tx * 8 + j];
                s += v[j]; s2 += v[j] * v[j];
            }
            #pragma unroll
            for (int w = 8; w >= 1; w >>= 1) {
                s  += __shfl_xor_sync(0xffffffffu, s, w);
                s2 += __shfl_xor_sync(0xffffffffu, s2, w);
            }
            float mu   = s * (1.0f / 128.0f);
            float var  = s2 * (1.0f / 128.0f) - mu * mu;
            float rstd = rsqrtf(var + 1e-5f);
            int gr = m0 + ty * 8 + i;
            if (gr < M) {
                #pragma unroll
                for (int j = 0; j < 8; j += 4) {
                    int gc = tx * 8 + j;
                    float4 o;
                    o.x = (v[j + 0] - mu) * rstd * P1[gc + 0] + P2[gc + 0];
                    o.y = (v[j + 1] - mu) * rstd * P1[gc + 1] + P2[gc + 1];
                    o.z = (v[j + 2] - mu) * rstd * P1[gc + 2] + P2[gc + 2];
                    o.w = (v[j + 3] - mu) * rstd * P1[gc + 3] + P2[gc + 3];
                    *(float4*)(C + (size_t)gr * 128 + gc) = o;
                }
            }
        }
        return;
    }

    #pragma unroll
    for (int i = 0; i < 8; i++) {
        int gr = m0 + ty * 8 + i;
        if (gr >= M) break;
        #pragma unroll
        for (int j = 0; j < 8; j += 4) {
            int gc = n0 + tx * 8 + j;
            float o[4];
            #pragma unroll
            for (int q = 0; q < 4; q++) {
                float v = acc[i][j + q] + bias[gc + q];
                if (EPI == 1) v = gelu_exact(v);
                if (EPI == 2) v += R[(size_t)gr * Nout + gc + q];
                o[q] = v;
            }
            *(float4*)(C + (size_t)gr * Nout + gc) =
                make_float4(o[0], o[1], o[2], o[3]);
        }
    }
}

// ---------------- edge pass A: logits + segment max (warp/edge) -----------
// X row layout (stride 384): [0,128)=xl, [128,256)=gA, [256,384)=gB
__global__ void edge_logits_k(const int* __restrict__ ei, const float* __restrict__ pos,
                              const float* __restrict__ X, const float* __restrict__ We,
                              const float* __restrict__ att,
                              float* __restrict__ logit, unsigned* __restrict__ amax, int E) {
    __shared__ float sW0[128], sW1[128], sAtt[128];
    int t = threadIdx.x;
    if (t < 128) {
        sW0[t]  = We[128 * 128 + t];
        sW1[t]  = We[129 * 128 + t];
        sAtt[t] = att[t];
    }
    __syncthreads();
    int e = (blockIdx.x * blockDim.x + t) >> 5;
    if (e >= E) return;
    int l = t & 31;
    int s = ei[e], d = ei[E + e];
    float2 ps = *(const float2*)(pos + 2 * (size_t)s);
    float2 pd = *(const float2*)(pos + 2 * (size_t)d);
    float rx = ps.x - pd.x, ry = ps.y - pd.y;
    float inv = 1.0f / (rx * rx + ry * ry + 1e-8f);
    float ox = -ry * inv, oy = rx * inv;
    const float* as = X + (size_t)s * 384 + 128;   // gA[src]
    const float* bd = X + (size_t)d * 384 + 256;   // gB[dst]
    float p[4];
    #pragma unroll
    for (int k = 0; k < 4; k++) {
        int ch = k * 32 + l;
        float v = as[ch] + bd[ch] + ox * sW0[ch] + oy * sW1[ch];
        v = v > 0.0f ? v : 0.2f * v;          // leaky_relu(0.2)
        p[k] = v * sAtt[ch];
    }
    #pragma unroll
    for (int w = 16; w >= 1; w >>= 1) {
        #pragma unroll
        for (int k = 0; k < 4; k++) p[k] += __shfl_xor_sync(0xffffffffu, p[k], w);
    }
    if (l == 0)
        *(float4*)(logit + (size_t)e * 4) = make_float4(p[0], p[1], p[2], p[3]);
    if (l < 4)
        atomicMax(&amax[(size_t)d * 4 + l], enc_float(p[l]));
}

// ---------------- edge pass B: ex = exp(logit - max), denom += ex ---------
__global__ void edge_exp_k(const int* __restrict__ ei, float* __restrict__ lg,
                           const unsigned* __restrict__ amax, float* __restrict__ denom, int E) {
    int e = blockIdx.x * blockDim.x + threadIdx.x;
    if (e >= E) return;
    int d = ei[E + e];
    float4 v = *(float4*)(lg + (size_t)e * 4);
    float r[4] = {v.x, v.y, v.z, v.w};
    #pragma unroll
    for (int k = 0; k < 4; k++) {
        float am = dec_float(amax[(size_t)d * 4 + k]);
        float ex = expf(r[k] - am);
        r[k] = ex;
        atomicAdd(&denom[(size_t)d * 4 + k], ex);
    }
    *(float4*)(lg + (size_t)e * 4) = make_float4(r[0], r[1], r[2], r[3]);
}

// -------- edge pass C: aggr[dst] += alpha * xl[src], vector red (warp/edge)
__global__ void edge_aggr_k(const int* __restrict__ ei, const float* __restrict__ lg,
                            const float* __restrict__ denom, const float* __restrict__ X,
                            float* __restrict__ aggr, int E) {
    int t = threadIdx.x;
    int e = (blockIdx.x * blockDim.x + t) >> 5;
    if (e >= E) return;
    int l = t & 31;
    int s = ei[e], d = ei[E + e];
    float4 ex = *(const float4*)(lg + (size_t)e * 4);
    float4 dn = *(const float4*)(denom + (size_t)d * 4);
    float a0 = ex.x / (dn.x + 1e-16f);
    float a1 = ex.y / (dn.y + 1e-16f);
    float a2 = ex.z / (dn.z + 1e-16f);
    float a3 = ex.w / (dn.w + 1e-16f);
    int h = l >> 3;  // lane l covers channels [4l,4l+4) -> head = l/8
    float al = (h < 2) ? (h == 0 ? a0 : a1) : (h == 2 ? a2 : a3);
    float4 v = *(const float4*)(X + (size_t)s * 384 + l * 4);  // xl[src] chans 4l..4l+3
    v.x *= al; v.y *= al; v.z *= al; v.w *= al;
    float* dst = aggr + (size_t)d * 128 + l * 4;   // 16B aligned
    asm volatile("red.global.add.v4.f32 [%0], {%1, %2, %3, %4};"
                 :: "l"(dst), "f"(v.x), "f"(v.y), "f"(v.z), "f"(v.w)
                 : "memory");
}

// ---------------- launch ----------------
extern "C" void kernel_launch(void* const* d_in, const int* in_sizes, int n_in,
                              void* d_out, int out_size) {
    const float* h_target = (const float*)d_in[0];
    const float* h_source = (const float*)d_in[1];
    const int*   ei       = (const int*)d_in[2];   // int32 (JAX x64 disabled)
    const float* pos      = (const float*)d_in[3];
    const float* t_emb    = (const float*)d_in[4];
    const float* gn_w     = (const float*)d_in[5];
    const float* gn_b     = (const float*)d_in[6];
    const float* fc_W     = (const float*)d_in[7];
    const float* fc_b     = (const float*)d_in[8];
    const float* Wl       = (const float*)d_in[9];
    const float* bl       = (const float*)d_in[10];
    const float* Wr       = (const float*)d_in[11];
    const float* br       = (const float*)d_in[12];
    const float* We       = (const float*)d_in[13];
    const float* att      = (const float*)d_in[14];
    const float* gat_b    = (const float*)d_in[15];
    const float* Wp       = (const float*)d_in[16];
    const float* bp       = (const float*)d_in[17];
    const float* ln_w     = (const float*)d_in[18];
    const float* ln_b     = (const float*)d_in[19];
    const float* W1       = (const float*)d_in[20];
    const float* b1       = (const float*)d_in[21];
    const float* W2       = (const float*)d_in[22];
    const float* b2       = (const float*)d_in[23];

    int n = in_sizes[0] / 128;
    int e = in_sizes[2] / 2;

    float* pool = nullptr;
    cudaGetSymbolAddress((void**)&pool, g_pool);
    float*    g_hmod  = pool + OFF_HMOD;              // later z
    float*    g_X     = pool + OFF_X;                 // later z2 (first 2 slots)
    float*    g_logit = pool + OFF_LOGIT;
    float*    g_aggr  = pool + OFF_AGGR;
    float*    g_denom = pool + OFF_DENOM;
    unsigned* g_amax  = (unsigned*)(pool + OFF_AMAX);
    float*    g_style = pool + OFF_MISC + MISC_STYLE;
    float*    g_bpp   = pool + OFF_MISC + MISC_BPP;
    float*    g_bcb   = pool + OFF_MISC + MISC_BCB;   // bias_cat
    float*    g_bcat  = pool + OFF_MISC + MISC_BCAT;  // Bcat 128x384
    float*    g_z     = g_hmod;
    float*    g_z2    = g_X;

    int mblocks = (n + 127) / 128;
    int eblocks = (e + 7) / 8;

    // 0) reset accumulators for this replay
    zero_k<<<512, 256>>>(g_amax, g_denom, g_aggr, n);
    // 1) tiny precompute: style, folded Wp bias, concatenated edge weights
    prep_k<<<1, 384>>>(t_emb, fc_W, fc_b, gat_b, Wp, bp, g_style, g_bpp);
    bcat_k<<<192, 256>>>(Wl, Wr, We, bl, br, g_bcat, g_bcb);
    // 2) AdaGN
    adagn_k<<<n, 128>>>(h_source, gn_w, gn_b, g_style, g_hmod, n);
    // 3) merged node GEMM: X = hmod @ [Wl | Wl+We | Wr-We] + [bl|bl|br]
    sgemm_k<0><<<dim3(mblocks, 3), 256>>>(g_hmod, 128, g_bcat, g_bcb,
                                          nullptr, nullptr, nullptr, g_X, n, 384);
    // 4) edge passes
    edge_logits_k<<<eblocks, 256>>>(ei, pos, g_X, We, att, g_logit, g_amax, e);
    edge_exp_k<<<(e + 255) / 256, 256>>>(ei, g_logit, g_amax, g_denom, e);
    edge_aggr_k<<<eblocks, 256>>>(ei, g_logit, g_denom, g_X, g_aggr, e);
    // 5) post-GAT GEMM with fused LayerNorm: z = LN(aggr@Wp + bpp)*ln_w + ln_b
    sgemm_k<3><<<dim3(mblocks, 1), 256>>>(g_aggr, 128, Wp, g_bpp,
                                          nullptr, ln_w, ln_b, g_z, n, 128);
    // 6) z2 = gelu(z@W1 + b1)
    sgemm_k<1><<<dim3(mblocks, 2), 256>>>(g_z, 128, W1, b1,
                                          nullptr, nullptr, nullptr, g_z2, n, 256);
    // 7) out = z2@W2 + b2 + h_target
    sgemm_k<2><<<dim3(mblocks, 1), 256>>>(g_z2, 256, W2, b2,
                                          h_target, nullptr, nullptr, (float*)d_out, n, 128);
}

// round 17
// speedup vs baseline: 1.2727x; 1.0969x over previous
#include <cuda_runtime.h>
#include <cuda_bf16.h>
#include <math.h>
#include <stdint.h>

// ---------------- problem constants ----------------
#define NMAX 50000
#define EMAX 800000

// ---------------- scratch pool (lifetime-carved) ----------------
// slot S = NMAX*128
//  [0,S)        hmod     (dead after merged GEMM; reused as y1 then z in-place)
//  [S,4S)       X = [xl|gA|gB] per row, stride 384 (dead after pass C; reused z2)
//  [4S,+4E)     logit / ex
//  then aggr (S), denom (4N), amax enc (4N),
//  misc: style 256, bpp 128, bias_cat 384, Bcat 128*384
#define SLOT ((size_t)NMAX * 128)
#define OFF_HMOD   ((size_t)0)
#define OFF_X      (SLOT)
#define OFF_LOGIT  (4 * SLOT)
#define OFF_AGGR   (OFF_LOGIT + (size_t)EMAX * 4)
#define OFF_DENOM  (OFF_AGGR + SLOT)
#define OFF_AMAX   (OFF_DENOM + (size_t)NMAX * 4)
#define OFF_MISC   (OFF_AMAX + (size_t)NMAX * 4)
#define MISC_STYLE 0
#define MISC_BPP   256
#define MISC_BCB   384
#define MISC_BCAT  1024
#define POOL_TOTAL (OFF_MISC + 1024 + (size_t)128 * 384 + 256)

__device__ __align__(16) float g_pool[POOL_TOTAL];

// ---------------- helpers ----------------
__device__ __forceinline__ unsigned enc_float(float f) {
    unsigned u = __float_as_uint(f);
    return (u & 0x80000000u) ? ~u : (u | 0x80000000u);
}
__device__ __forceinline__ float dec_float(unsigned u) {
    return (u & 0x80000000u) ? __uint_as_float(u ^ 0x80000000u)
                             : __uint_as_float(~u);
}
__device__ __forceinline__ float gelu_exact(float x) {
    return 0.5f * x * (1.0f + erff(x * 0.70710678118654752f));
}
__device__ __forceinline__ void split_tf32(float x, uint32_t& hi, uint32_t& lo) {
    asm("cvt.rna.tf32.f32 %0, %1;" : "=r"(hi) : "f"(x));
    float r = x - __uint_as_float(hi);
    asm("cvt.rna.tf32.f32 %0, %1;" : "=r"(lo) : "f"(r));
}
#define MMA_TF32(c, a0, a1, a2, a3, b0, b1)                                   \
    asm volatile(                                                             \
        "mma.sync.aligned.m16n8k8.row.col.f32.tf32.tf32.f32 "                 \
        "{%0,%1,%2,%3}, {%4,%5,%6,%7}, {%8,%9}, {%0,%1,%2,%3};"               \
        : "+f"((c)[0]), "+f"((c)[1]), "+f"((c)[2]), "+f"((c)[3])              \
        : "r"(a0), "r"(a1), "r"(a2), "r"(a3), "r"(b0), "r"(b1))

// ---------------- zero accumulators ----------------
__global__ void zero_k(unsigned* __restrict__ amax, float* __restrict__ denom,
                       float* __restrict__ aggr, int n) {
    int i = blockIdx.x * blockDim.x + threadIdx.x;
    int stride = gridDim.x * blockDim.x;
    int n4 = n * 4;
    for (int j = i; j < n4; j += stride) { amax[j] = 0u; denom[j] = 0.0f; }
    int n128 = n * 128;
    for (int j = i; j < n128; j += stride) aggr[j] = 0.0f;
}

// ---------------- tiny precompute ----------------
__global__ void prep_k(const float* __restrict__ t_emb, const float* __restrict__ fc_W,
                       const float* __restrict__ fc_b, const float* __restrict__ gat_b,
                       const float* __restrict__ Wp, const float* __restrict__ bp,
                       float* __restrict__ style, float* __restrict__ bpp) {
    int j = threadIdx.x;  // 384 threads
    if (j < 256) {
        float s = fc_b[j];
        #pragma unroll 4
        for (int k = 0; k < 128; k++) s += t_emb[k] * fc_W[k * 256 + j];
        style[j] = s;
    } else {
        int c = j - 256;
        float s = bp[c];
        #pragma unroll 4
        for (int k = 0; k < 128; k++) s += gat_b[k] * Wp[k * 128 + c];
        bpp[c] = s;
    }
}

// -------- build Bcat = [Wl | Wl+We_phys | Wr-We_phys] (128x384) + bias_cat --
__global__ void bcat_k(const float* __restrict__ Wl, const float* __restrict__ Wr,
                       const float* __restrict__ We, const float* __restrict__ bl,
                       const float* __restrict__ br, float* __restrict__ Bcat,
                       float* __restrict__ bias_cat) {
    int i = blockIdx.x * blockDim.x + threadIdx.x;
    if (i < 128 * 384) {
        int k = i / 384, c = i % 384;
        float v;
        if (c < 128)      v = Wl[k * 128 + c];
        else if (c < 256) v = Wl[k * 128 + (c - 128)] + We[k * 128 + (c - 128)];
        else              v = Wr[k * 128 + (c - 256)] - We[k * 128 + (c - 256)];
        Bcat[i] = v;
    }
    if (i < 384)
        bias_cat[i] = (i < 128) ? bl[i] : (i < 256 ? bl[i - 128] : br[i - 256]);
}

// ---------------- AdaGN: warp per node, float4 lanes ----------------
__global__ void adagn_k(const float* __restrict__ hs, const float* __restrict__ gn_w,
                        const float* __restrict__ gn_b, const float* __restrict__ style,
                        float* __restrict__ hmod, int n) {
    int node = blockIdx.x * 8 + (threadIdx.x >> 5);
    if (node >= n) return;
    int lane = threadIdx.x & 31;  // 4 channels per lane; 16-chan group = 4 lanes
    float4 x = *(const float4*)(hs + (size_t)node * 128 + lane * 4);
    float s  = x.x + x.y + x.z + x.w;
    float s2 = x.x * x.x + x.y * x.y + x.z * x.z + x.w * x.w;
    s  += __shfl_xor_sync(0xffffffffu, s, 1);
    s  += __shfl_xor_sync(0xffffffffu, s, 2);
    s2 += __shfl_xor_sync(0xffffffffu, s2, 1);
    s2 += __shfl_xor_sync(0xffffffffu, s2, 2);
    float mu   = s * (1.0f / 16.0f);
    float var  = s2 * (1.0f / 16.0f) - mu * mu;
    float rstd = rsqrtf(var + 1e-5f);
    float4 w  = *(const float4*)(gn_w + lane * 4);
    float4 bb = *(const float4*)(gn_b + lane * 4);
    float4 gm = *(const float4*)(style + lane * 4);
    float4 bt = *(const float4*)(style + 128 + lane * 4);
    float4 o;
    o.x = ((x.x - mu) * rstd * w.x + bb.x) * (1.0f + gm.x) + bt.x;
    o.y = ((x.y - mu) * rstd * w.y + bb.y) * (1.0f + gm.y) + bt.y;
    o.z = ((x.z - mu) * rstd * w.z + bb.z) * (1.0f + gm.z) + bt.z;
    o.w = ((x.w - mu) * rstd * w.w + bb.w) * (1.0f + gm.w) + bt.w;
    *(float4*)(hmod + (size_t)node * 128 + lane * 4) = o;
}

// ------------- tf32 tensor-core GEMM (3xTF32 precision split) --------------
// C(MxN) = A(MxK) @ B(KxN) + bias ; EPI 0: none ; 1: gelu ; 2: +R residual
// Block: 256 threads = 8 warps as 2(m)x4(n); warp tile 64x32; block tile 128x128.
template <int EPI>
__global__ __launch_bounds__(256)
void tf32gemm_k(const float* __restrict__ A, int K, const float* __restrict__ B,
                const float* __restrict__ bias, const float* __restrict__ R,
                float* __restrict__ C, int M, int Nout) {
    __shared__ float As[128][36];   // pad 36 -> frag LDS conflict-free
    __shared__ float Bs[32][136];   // pad 136 -> frag LDS conflict-free
    int t = threadIdx.x;
    int lane = t & 31, wid = t >> 5;
    int wm = wid >> 2, wn = wid & 3;      // warp grid 2x4
    int g = lane >> 2, tig = lane & 3;    // mma group / thread-in-group
    int m0 = blockIdx.x * 128, n0 = blockIdx.y * 128;

    float acc[4][4][4];  // [mt][nt][reg]
    #pragma unroll
    for (int i = 0; i < 4; i++)
        #pragma unroll
        for (int j = 0; j < 4; j++) {
            acc[i][j][0] = 0.f; acc[i][j][1] = 0.f;
            acc[i][j][2] = 0.f; acc[i][j][3] = 0.f;
        }

    for (int k0 = 0; k0 < K; k0 += 32) {
        // stage A: 128 rows x 32 k
        #pragma unroll
        for (int i = 0; i < 4; i++) {
            int idx = t + i * 256;
            int row = idx >> 3, c4 = (idx & 7) * 4;
            int gr = m0 + row; if (gr > M - 1) gr = M - 1;
            float4 v = *(const float4*)(A + (size_t)gr * K + k0 + c4);
            *(float4*)&As[row][c4] = v;
        }
        // stage B: 32 k x 128 cols
        #pragma unroll
        for (int i = 0; i < 4; i++) {
            int idx = t + i * 256;
            int row = idx >> 5, c4 = (idx & 31) * 4;
            float4 v = *(const float4*)(B + (size_t)(k0 + row) * Nout + n0 + c4);
            *(float4*)&Bs[row][c4] = v;
        }
        __syncthreads();
        #pragma unroll
        for (int kk = 0; kk < 4; kk++) {
            int kb = kk * 8;
            uint32_t bh[4][2], blo[4][2];
            #pragma unroll
            for (int nt = 0; nt < 4; nt++) {
                int col = wn * 32 + nt * 8 + g;
                split_tf32(Bs[kb + tig][col],     bh[nt][0], blo[nt][0]);
                split_tf32(Bs[kb + tig + 4][col], bh[nt][1], blo[nt][1]);
            }
            #pragma unroll
            for (int mt = 0; mt < 4; mt++) {
                int row = wm * 64 + mt * 16;
                uint32_t ah[4], alo[4];
                split_tf32(As[row + g][kb + tig],         ah[0], alo[0]);
                split_tf32(As[row + 8 + g][kb + tig],     ah[1], alo[1]);
                split_tf32(As[row + g][kb + tig + 4],     ah[2], alo[2]);
                split_tf32(As[row + 8 + g][kb + tig + 4], ah[3], alo[3]);
                #pragma unroll
                for (int nt = 0; nt < 4; nt++) {
                    MMA_TF32(acc[mt][nt], alo[0], alo[1], alo[2], alo[3],
                             bh[nt][0], bh[nt][1]);             // lo*hi
                    MMA_TF32(acc[mt][nt], ah[0], ah[1], ah[2], ah[3],
                             blo[nt][0], blo[nt][1]);           // hi*lo
                    MMA_TF32(acc[mt][nt], ah[0], ah[1], ah[2], ah[3],
                             bh[nt][0], bh[nt][1]);             // hi*hi
                }
            }
        }
        __syncthreads();
    }

    // epilogue: thread owns rows {r0, r0+8} x col pairs
    #pragma unroll
    for (int mt = 0; mt < 4; mt++) {
        int r0 = m0 + wm * 64 + mt * 16 + g;
        #pragma unroll
        for (int nt = 0; nt < 4; nt++) {
            int col = n0 + wn * 32 + nt * 8 + 2 * tig;
            float b0 = bias[col], b1 = bias[col + 1];
            float v0 = acc[mt][nt][0] + b0, v1 = acc[mt][nt][1] + b1;
            float v2 = acc[mt][nt][2] + b0, v3 = acc[mt][nt][3] + b1;
            if (EPI == 1) {
                v0 = gelu_exact(v0); v1 = gelu_exact(v1);
                v2 = gelu_exact(v2); v3 = gelu_exact(v3);
            }
            if (r0 < M) {
                if (EPI == 2) {
                    float2 rr = *(const float2*)(R + (size_t)r0 * Nout + col);
                    v0 += rr.x; v1 += rr.y;
                }
                *(float2*)(C + (size_t)r0 * Nout + col) = make_float2(v0, v1);
            }
            if (r0 + 8 < M) {
                if (EPI == 2) {
                    float2 rr = *(const float2*)(R + (size_t)(r0 + 8) * Nout + col);
                    v2 += rr.x; v3 += rr.y;
                }
                *(float2*)(C + (size_t)(r0 + 8) * Nout + col) = make_float2(v2, v3);
            }
        }
    }
}

// ---------------- edge pass A: logits + segment max (warp/edge) -----------
// X row layout (stride 384): [0,128)=xl, [128,256)=gA, [256,384)=gB
__global__ void edge_logits_k(const int* __restrict__ ei, const float* __restrict__ pos,
                              const float* __restrict__ X, const float* __restrict__ We,
                              const float* __restrict__ att,
                              float* __restrict__ logit, unsigned* __restrict__ amax, int E) {
    __shared__ float sW0[128], sW1[128], sAtt[128];
    int t = threadIdx.x;
    if (t < 128) {
        sW0[t]  = We[128 * 128 + t];
        sW1[t]  = We[129 * 128 + t];
        sAtt[t] = att[t];
    }
    __syncthreads();
    int e = (blockIdx.x * blockDim.x + t) >> 5;
    if (e >= E) return;
    int l = t & 31;
    int s = ei[e], d = ei[E + e];
    float2 ps = *(const float2*)(pos + 2 * (size_t)s);
    float2 pd = *(const float2*)(pos + 2 * (size_t)d);
    float rx = ps.x - pd.x, ry = ps.y - pd.y;
    float inv = 1.0f / (rx * rx + ry * ry + 1e-8f);
    float ox = -ry * inv, oy = rx * inv;
    const float* as = X + (size_t)s * 384 + 128;   // gA[src]
    const float* bd = X + (size_t)d * 384 + 256;   // gB[dst]
    float p[4];
    #pragma unroll
    for (int k = 0; k < 4; k++) {
        int ch = k * 32 + l;
        float v = as[ch] + bd[ch] + ox * sW0[ch] + oy * sW1[ch];
        v = v > 0.0f ? v : 0.2f * v;          // leaky_relu(0.2)
        p[k] = v * sAtt[ch];
    }
    #pragma unroll
    for (int w = 16; w >= 1; w >>= 1) {
        #pragma unroll
        for (int k = 0; k < 4; k++) p[k] += __shfl_xor_sync(0xffffffffu, p[k], w);
    }
    if (l == 0)
        *(float4*)(logit + (size_t)e * 4) = make_float4(p[0], p[1], p[2], p[3]);
    if (l < 4)
        atomicMax(&amax[(size_t)d * 4 + l], enc_float(p[l]));
}

// ---------------- edge pass B: ex = exp(logit - max), denom += ex ---------
__global__ void edge_exp_k(const int* __restrict__ ei, float* __restrict__ lg,
                           const unsigned* __restrict__ amax, float* __restrict__ denom, int E) {
    int e = blockIdx.x * blockDim.x + threadIdx.x;
    if (e >= E) return;
    int d = ei[E + e];
    float4 v = *(float4*)(lg + (size_t)e * 4);
    float r[4] = {v.x, v.y, v.z, v.w};
    #pragma unroll
    for (int k = 0; k < 4; k++) {
        float am = dec_float(amax[(size_t)d * 4 + k]);
        float ex = expf(r[k] - am);
        r[k] = ex;
        atomicAdd(&denom[(size_t)d * 4 + k], ex);
    }
    *(float4*)(lg + (size_t)e * 4) = make_float4(r[0], r[1], r[2], r[3]);
}

// -------- edge pass C: aggr[dst] += alpha * xl[src], vector red (warp/edge)
__global__ void edge_aggr_k(const int* __restrict__ ei, const float* __restrict__ lg,
                            const float* __restrict__ denom, const float* __restrict__ X,
                            float* __restrict__ aggr, int E) {
    int t = threadIdx.x;
    int e = (blockIdx.x * blockDim.x + t) >> 5;
    if (e >= E) return;
    int l = t & 31;
    int s = ei[e], d = ei[E + e];
    float4 ex = *(const float4*)(lg + (size_t)e * 4);
    float4 dn = *(const float4*)(denom + (size_t)d * 4);
    float a0 = ex.x / (dn.x + 1e-16f);
    float a1 = ex.y / (dn.y + 1e-16f);
    float a2 = ex.z / (dn.z + 1e-16f);
    float a3 = ex.w / (dn.w + 1e-16f);
    int h = l >> 3;  // lane l covers channels [4l,4l+4) -> head = l/8
    float al = (h < 2) ? (h == 0 ? a0 : a1) : (h == 2 ? a2 : a3);
    float4 v = *(const float4*)(X + (size_t)s * 384 + l * 4);  // xl[src]
    v.x *= al; v.y *= al; v.z *= al; v.w *= al;
    float* dst = aggr + (size_t)d * 128 + l * 4;   // 16B aligned
    asm volatile("red.global.add.v4.f32 [%0], {%1, %2, %3, %4};"
                 :: "l"(dst), "f"(v.x), "f"(v.y), "f"(v.z), "f"(v.w)
                 : "memory");
}

// ---------------- LayerNorm over D=128 (in-place safe) ----------------
__global__ void ln_k(const float* __restrict__ y, const float* __restrict__ w,
                     const float* __restrict__ b, float* __restrict__ z, int n) {
    int node = blockIdx.x;
    int t = threadIdx.x;  // 128
    float x = y[(size_t)node * 128 + t];
    float s = x, s2 = x * x;
    #pragma unroll
    for (int wdt = 16; wdt >= 1; wdt >>= 1) {
        s  += __shfl_xor_sync(0xffffffffu, s, wdt);
        s2 += __shfl_xor_sync(0xffffffffu, s2, wdt);
    }
    __shared__ float ss[4], ss2[4];
    int wid = t >> 5;
    if ((t & 31) == 0) { ss[wid] = s; ss2[wid] = s2; }
    __syncthreads();
    s  = ss[0] + ss[1] + ss[2] + ss[3];
    s2 = ss2[0] + ss2[1] + ss2[2] + ss2[3];
    float mu  = s * (1.0f / 128.0f);
    float var = s2 * (1.0f / 128.0f) - mu * mu;
    z[(size_t)node * 128 + t] = (x - mu) * rsqrtf(var + 1e-5f) * w[t] + b[t];
}

// ---------------- launch ----------------
extern "C" void kernel_launch(void* const* d_in, const int* in_sizes, int n_in,
                              void* d_out, int out_size) {
    const float* h_target = (const float*)d_in[0];
    const float* h_source = (const float*)d_in[1];
    const int*   ei       = (const int*)d_in[2];   // int32 (JAX x64 disabled)
    const float* pos      = (const float*)d_in[3];
    const float* t_emb    = (const float*)d_in[4];
    const float* gn_w     = (const float*)d_in[5];
    const float* gn_b     = (const float*)d_in[6];
    const float* fc_W     = (const float*)d_in[7];
    const float* fc_b     = (const float*)d_in[8];
    const float* Wl       = (const float*)d_in[9];
    const float* bl       = (const float*)d_in[10];
    const float* Wr       = (const float*)d_in[11];
    const float* br       = (const float*)d_in[12];
    const float* We       = (const float*)d_in[13];
    const float* att      = (const float*)d_in[14];
    const float* gat_b    = (const float*)d_in[15];
    const float* Wp       = (const float*)d_in[16];
    const float* bp       = (const float*)d_in[17];
    const float* ln_w     = (const float*)d_in[18];
    const float* ln_b     = (const float*)d_in[19];
    const float* W1       = (const float*)d_in[20];
    const float* b1       = (const float*)d_in[21];
    const float* W2       = (const float*)d_in[22];
    const float* b2       = (const float*)d_in[23];

    int n = in_sizes[0] / 128;
    int e = in_sizes[2] / 2;

    float* pool = nullptr;
    cudaGetSymbolAddress((void**)&pool, g_pool);
    float*    g_hmod  = pool + OFF_HMOD;              // later y1 / z (in place)
    float*    g_X     = pool + OFF_X;                 // later z2
    float*    g_logit = pool + OFF_LOGIT;
    float*    g_aggr  = pool + OFF_AGGR;
    float*    g_denom = pool + OFF_DENOM;
    unsigned* g_amax  = (unsigned*)(pool + OFF_AMAX);
    float*    g_style = pool + OFF_MISC + MISC_STYLE;
    float*    g_bpp   = pool + OFF_MISC + MISC_BPP;
    float*    g_bcb   = pool + OFF_MISC + MISC_BCB;   // bias_cat
    float*    g_bcat  = pool + OFF_MISC + MISC_BCAT;  // Bcat 128x384
    float*    g_y1    = g_hmod;
    float*    g_z     = g_hmod;
    float*    g_z2    = g_X;

    int mblocks = (n + 127) / 128;
    int eblocks = (e + 7) / 8;

    // 0) reset accumulators for this replay
    zero_k<<<512, 256>>>(g_amax, g_denom, g_aggr, n);
    // 1) tiny precompute: style, folded Wp bias, concatenated edge weights
    prep_k<<<1, 384>>>(t_emb, fc_W, fc_b, gat_b, Wp, bp, g_style, g_bpp);
    bcat_k<<<192, 256>>>(Wl, Wr, We, bl, br, g_bcat, g_bcb);
    // 2) AdaGN
    adagn_k<<<(n + 7) / 8, 256>>>(h_source, gn_w, gn_b, g_style, g_hmod, n);
    // 3) merged node GEMM: X = hmod @ [Wl | Wl+We | Wr-We] + [bl|bl|br]
    tf32gemm_k<0><<<dim3(mblocks, 3), 256>>>(g_hmod, 128, g_bcat, g_bcb,
                                             nullptr, g_X, n, 384);
    // 4) edge passes
    edge_logits_k<<<eblocks, 256>>>(ei, pos, g_X, We, att, g_logit, g_amax, e);
    edge_exp_k<<<(e + 255) / 256, 256>>>(ei, g_logit, g_amax, g_denom, e);
    edge_aggr_k<<<eblocks, 256>>>(ei, g_logit, g_denom, g_X, g_aggr, e);
    // 5) post-GAT: y1 = aggr@Wp + bpp ; z = LN(y1) in place
    tf32gemm_k<0><<<dim3(mblocks, 1), 256>>>(g_aggr, 128, Wp, g_bpp,
                                             nullptr, g_y1, n, 128);
    ln_k<<<n, 128>>>(g_y1, ln_w, ln_b, g_z, n);
    // 6) z2 = gelu(z@W1 + b1)
    tf32gemm_k<1><<<dim3(mblocks, 2), 256>>>(g_z, 128, W1, b1,
                                             nullptr, g_z2, n, 256);
    // 7) out = z2@W2 + b2 + h_target
    tf32gemm_k<2><<<dim3(mblocks, 1), 256>>>(g_z2, 256, W2, b2,
                                             h_target, (float*)d_out, n, 128);
}